// round 3
// baseline (speedup 1.0000x reference)
#include <cuda_runtime.h>
#include <stdint.h>

#define NN   50000
#define EE   800000
#define INF  128
#define OUTF 64
#define HEADS 4
#define HN   (HEADS * NN)       // 200000
#define OUT_COLS (HEADS * OUTF) // 256
#define NEG_SLOPE 0.2f
#define EPSV 1e-8f

// ---------------- scratch (device globals; no allocation allowed) ----------------
__device__ __align__(16) float g_Wh[HEADS * NN * OUTF];   // [h][n][f]  51.2 MB
__device__ float g_es[HN];     // e_src per (h,n)
__device__ float g_ed[HN];     // e_dst per (h,n)
__device__ float g_emax[HN];   // running max(seg_max, 0) per (h,n)
__device__ float g_esum[HN];   // exp-sum per (h,n)
__device__ __align__(16) float g_expe[HEADS * EE];        // exp(e - emax) 12.8 MB

// ---------------- zero init: d_out + emax + esum ----------------
__global__ void zero_kernel(float* __restrict__ out, int out_size) {
    int idx = blockIdx.x * blockDim.x + threadIdx.x;
    int total = out_size + 2 * HN;
    if (idx >= total) return;
    if (idx < out_size) {
        out[idx] = 0.0f;
    } else {
        int j = idx - out_size;
        if (j < HN) g_emax[j] = 0.0f;
        else        g_esum[j - HN] = 0.0f;
    }
}

// ---------------- SGEMM: Wh[h][n][f] = sum_k x[n][k] * W[h][k][f] ----------------
__global__ void gemm_kernel(const float* __restrict__ x, const float* __restrict__ W) {
    __shared__ float As[64][64];
    __shared__ float Bs[64][64];
    int bm = blockIdx.x;
    int h  = blockIdx.y;
    int tid = threadIdx.x;
    int row0 = bm * 64;

    int tr = tid >> 4;   // 0..15
    int tc = tid & 15;   // 0..15
    float acc[4][4];
#pragma unroll
    for (int i = 0; i < 4; i++)
#pragma unroll
        for (int j = 0; j < 4; j++) acc[i][j] = 0.0f;

    const float4* Wb4 = reinterpret_cast<const float4*>(W + (size_t)h * INF * OUTF);

    for (int kt = 0; kt < 2; kt++) {
#pragma unroll
        for (int i = 0; i < 4; i++) {
            int lin = tid + 256 * i;          // float4 index
            int r  = lin >> 4;
            int c4 = lin & 15;
            float4 v = make_float4(0.f, 0.f, 0.f, 0.f);
            int gr = row0 + r;
            if (gr < NN)
                v = reinterpret_cast<const float4*>(x + (size_t)gr * INF + kt * 64)[c4];
            *reinterpret_cast<float4*>(&As[r][c4 * 4]) = v;
        }
#pragma unroll
        for (int i = 0; i < 4; i++) {
            int lin = tid + 256 * i;
            int kk = lin >> 4;
            int c4 = lin & 15;
            *reinterpret_cast<float4*>(&Bs[kk][c4 * 4]) = Wb4[(kt * 64 + kk) * 16 + c4];
        }
        __syncthreads();

#pragma unroll 8
        for (int kk = 0; kk < 64; kk++) {
            float a[4];
#pragma unroll
            for (int i = 0; i < 4; i++) a[i] = As[tr * 4 + i][kk];
            float4 bv = *reinterpret_cast<float4*>(&Bs[kk][tc * 4]);
            float b[4] = {bv.x, bv.y, bv.z, bv.w};
#pragma unroll
            for (int i = 0; i < 4; i++)
#pragma unroll
                for (int j = 0; j < 4; j++) acc[i][j] = fmaf(a[i], b[j], acc[i][j]);
        }
        __syncthreads();
    }

#pragma unroll
    for (int i = 0; i < 4; i++) {
        int gr = row0 + tr * 4 + i;
        if (gr < NN) {
            float4 v = make_float4(acc[i][0], acc[i][1], acc[i][2], acc[i][3]);
            *reinterpret_cast<float4*>(g_Wh + ((size_t)h * NN + gr) * OUTF + tc * 4) = v;
        }
    }
}

// ---------------- per-(h,n) attention logits: warp per row ----------------
__global__ void escore_kernel(const float* __restrict__ a_src, const float* __restrict__ a_dst) {
    int gw = (blockIdx.x * blockDim.x + threadIdx.x) >> 5;  // == h*NN + n
    int lane = threadIdx.x & 31;
    if (gw >= HN) return;
    int h = gw / NN;
    float2 wh = reinterpret_cast<const float2*>(g_Wh + (size_t)gw * OUTF)[lane];
    float2 as = reinterpret_cast<const float2*>(a_src + h * OUTF)[lane];
    float2 ad = reinterpret_cast<const float2*>(a_dst + h * OUTF)[lane];
    float s = wh.x * as.x + wh.y * as.y;
    float d = wh.x * ad.x + wh.y * ad.y;
#pragma unroll
    for (int o = 16; o; o >>= 1) {
        s += __shfl_xor_sync(0xffffffffu, s, o);
        d += __shfl_xor_sync(0xffffffffu, d, o);
    }
    if (lane == 0) { g_es[gw] = s; g_ed[gw] = d; }
}

// ---------------- edge pass 1: segment max (only positives matter) ----------------
__global__ void edge_max_kernel(const int* __restrict__ ei) {
    int e = blockIdx.x * blockDim.x + threadIdx.x;
    if (e >= EE) return;
    int s = ei[e];
    int d = ei[EE + e];
    if ((unsigned)s >= NN || (unsigned)d >= NN) return;  // safety: never trap
#pragma unroll
    for (int h = 0; h < HEADS; h++) {
        float t = g_es[h * NN + s] + g_ed[h * NN + d];
        t = t > 0.f ? t : t * NEG_SLOPE;
        if (t > 0.f)  // init is 0; negatives never beat max(seg_max, 0)
            atomicMax(reinterpret_cast<int*>(&g_emax[h * NN + d]), __float_as_int(t));
    }
}

// ---------------- edge pass 2: exp + segment sum ----------------
__global__ void edge_exp_kernel(const int* __restrict__ ei) {
    int e = blockIdx.x * blockDim.x + threadIdx.x;
    if (e >= EE) return;
    int s = ei[e];
    int d = ei[EE + e];
    if ((unsigned)s >= NN || (unsigned)d >= NN) return;
#pragma unroll
    for (int h = 0; h < HEADS; h++) {
        float t = g_es[h * NN + s] + g_ed[h * NN + d];
        t = t > 0.f ? t : t * NEG_SLOPE;
        float w = __expf(t - g_emax[h * NN + d]);
        g_expe[h * EE + e] = w;
        atomicAdd(&g_esum[h * NN + d], w);
    }
}

// ---------------- edge pass 3: weighted scatter-aggregate ----------------
// warp per edge; each lane covers two (head, float4) slots of the 256-col row.
__global__ void edge_agg_kernel(const int* __restrict__ ei, float* __restrict__ out) {
    int gw = (blockIdx.x * blockDim.x + threadIdx.x) >> 5;  // edge id
    int lane = threadIdx.x & 31;
    if (gw >= EE) return;
    int s = ei[gw];
    int d = ei[EE + gw];
    if ((unsigned)s >= NN || (unsigned)d >= NN) return;
#pragma unroll
    for (int i = 0; i < 2; i++) {
        int slot = lane + 32 * i;        // 0..63
        int h   = slot >> 4;             // 0..3
        int f4  = slot & 15;             // float4 index within head
        float att = g_expe[(size_t)h * EE + gw] / (g_esum[h * NN + d] + EPSV);
        float4 v = reinterpret_cast<const float4*>(
            g_Wh + ((size_t)h * NN + s) * OUTF)[f4];
        float rx = v.x * att, ry = v.y * att, rz = v.z * att, rw = v.w * att;
        float* addr = out + (size_t)d * OUT_COLS + h * OUTF + f4 * 4;
        asm volatile("red.global.add.v4.f32 [%0], {%1, %2, %3, %4};"
                     :: "l"(addr), "f"(rx), "f"(ry), "f"(rz), "f"(rw)
                     : "memory");
    }
}

// ---------------- launch ----------------
extern "C" void kernel_launch(void* const* d_in, const int* in_sizes, int n_in,
                              void* d_out, int out_size) {
    // Resolve inputs by element count (robust to metadata ordering).
    const float* x     = nullptr;   // 50000*128   = 6400000 f32
    const int*   ei    = nullptr;   // 2*800000    = 1600000 i32 (jax demotes int64)
    const float* W     = nullptr;   // 4*128*64    = 32768 f32
    const float* a_src = nullptr;   // 4*64*1      = 256 f32 (first)
    const float* a_dst = nullptr;   // 4*64*1      = 256 f32 (second)
    for (int i = 0; i < n_in; i++) {
        int sz = in_sizes[i];
        if      (sz == NN * INF)            x  = (const float*)d_in[i];
        else if (sz == 2 * EE)              ei = (const int*)d_in[i];
        else if (sz == HEADS * INF * OUTF)  W  = (const float*)d_in[i];
        else if (sz == HEADS * OUTF) {
            if (!a_src) a_src = (const float*)d_in[i];
            else        a_dst = (const float*)d_in[i];
        }
    }
    float* out = (float*)d_out;

    {
        int total = out_size + 2 * HN;
        zero_kernel<<<(total + 255) / 256, 256>>>(out, out_size);
    }
    {
        dim3 grid((NN + 63) / 64, HEADS);
        gemm_kernel<<<grid, 256>>>(x, W);
    }
    escore_kernel<<<(HN * 32 + 255) / 256, 256>>>(a_src, a_dst);
    edge_max_kernel<<<(EE + 255) / 256, 256>>>(ei);
    edge_exp_kernel<<<(EE + 255) / 256, 256>>>(ei);
    edge_agg_kernel<<<(EE * 32 + 255) / 256, 256>>>(ei, out);
}

// round 4
// speedup vs baseline: 1.9425x; 1.9425x over previous
#include <cuda_runtime.h>
#include <stdint.h>

#define NN   50000
#define EE   800000
#define INF  128
#define OUTF 64
#define HEADS 4
#define OUT_COLS (HEADS * OUTF) // 256
#define NEG_SLOPE 0.2f
#define EPSV 1e-8f
#define NB_SCAN 49               // ceil(50000/1024)

// ---------------- scratch (device globals) ----------------
__device__ __align__(16) float g_Wh[(size_t)NN * OUT_COLS]; // [n][h*64+f] 51.2 MB
__device__ __align__(16) float4 g_es4[NN];    // per-node src logits, 4 heads
__device__ __align__(16) float4 g_ed4[NN];    // per-node dst logits, 4 heads
__device__ __align__(16) float4 g_rinv4[NN];  // 1/(expsum+eps), 4 heads
__device__ __align__(16) float4 g_att4[EE];   // per-edge exp(t-max), 4 heads (CSR order)
__device__ int g_cnt[NN];
__device__ int g_rowptr[NN];
__device__ int g_cursor[NN];
__device__ int g_srcs[EE];
__device__ int g_bsum[64];

// ---------------- init: zero histogram ----------------
__global__ void init_kernel() {
    int i = blockIdx.x * blockDim.x + threadIdx.x;
    if (i < NN) g_cnt[i] = 0;
}

// ---------------- SGEMM: Wh[n][h*64+f] = sum_k x[n][k] * W[h][k][f] ----------------
__global__ void gemm_kernel(const float* __restrict__ x, const float* __restrict__ W) {
    __shared__ float As[64][64];
    __shared__ float Bs[64][64];
    int bm = blockIdx.x;
    int h  = blockIdx.y;
    int tid = threadIdx.x;
    int row0 = bm * 64;

    int tr = tid >> 4;   // 0..15
    int tc = tid & 15;   // 0..15
    float acc[4][4];
#pragma unroll
    for (int i = 0; i < 4; i++)
#pragma unroll
        for (int j = 0; j < 4; j++) acc[i][j] = 0.0f;

    const float4* Wb4 = reinterpret_cast<const float4*>(W + (size_t)h * INF * OUTF);

    for (int kt = 0; kt < 2; kt++) {
#pragma unroll
        for (int i = 0; i < 4; i++) {
            int lin = tid + 256 * i;
            int r  = lin >> 4;
            int c4 = lin & 15;
            float4 v = make_float4(0.f, 0.f, 0.f, 0.f);
            int gr = row0 + r;
            if (gr < NN)
                v = reinterpret_cast<const float4*>(x + (size_t)gr * INF + kt * 64)[c4];
            *reinterpret_cast<float4*>(&As[r][c4 * 4]) = v;
        }
#pragma unroll
        for (int i = 0; i < 4; i++) {
            int lin = tid + 256 * i;
            int kk = lin >> 4;
            int c4 = lin & 15;
            *reinterpret_cast<float4*>(&Bs[kk][c4 * 4]) = Wb4[(kt * 64 + kk) * 16 + c4];
        }
        __syncthreads();

#pragma unroll 8
        for (int kk = 0; kk < 64; kk++) {
            float a[4];
#pragma unroll
            for (int i = 0; i < 4; i++) a[i] = As[tr * 4 + i][kk];
            float4 bv = *reinterpret_cast<float4*>(&Bs[kk][tc * 4]);
            float b[4] = {bv.x, bv.y, bv.z, bv.w};
#pragma unroll
            for (int i = 0; i < 4; i++)
#pragma unroll
                for (int j = 0; j < 4; j++) acc[i][j] = fmaf(a[i], b[j], acc[i][j]);
        }
        __syncthreads();
    }

#pragma unroll
    for (int i = 0; i < 4; i++) {
        int gr = row0 + tr * 4 + i;
        if (gr < NN) {
            float4 v = make_float4(acc[i][0], acc[i][1], acc[i][2], acc[i][3]);
            *reinterpret_cast<float4*>(g_Wh + (size_t)gr * OUT_COLS + h * OUTF + tc * 4) = v;
        }
    }
}

// ---------------- logits: warp per node, all 4 heads ----------------
__global__ void escore_kernel(const float* __restrict__ a_src, const float* __restrict__ a_dst) {
    int n = (blockIdx.x * blockDim.x + threadIdx.x) >> 5;
    int lane = threadIdx.x & 31;
    if (n >= NN) return;
    // lane covers cols [lane*8, lane*8+8) of the 256-col row; head = lane>>3
    const float4* row = reinterpret_cast<const float4*>(g_Wh + (size_t)n * OUT_COLS);
    float4 q0 = row[lane * 2];
    float4 q1 = row[lane * 2 + 1];
    int h = lane >> 3;
    int cb = (lane & 7) * 2;   // float4 index within head
    const float4* as4 = reinterpret_cast<const float4*>(a_src + h * OUTF);
    const float4* ad4 = reinterpret_cast<const float4*>(a_dst + h * OUTF);
    float4 s0 = as4[cb], s1 = as4[cb + 1];
    float4 d0 = ad4[cb], d1 = ad4[cb + 1];
    float s = q0.x*s0.x + q0.y*s0.y + q0.z*s0.z + q0.w*s0.w
            + q1.x*s1.x + q1.y*s1.y + q1.z*s1.z + q1.w*s1.w;
    float d = q0.x*d0.x + q0.y*d0.y + q0.z*d0.z + q0.w*d0.w
            + q1.x*d1.x + q1.y*d1.y + q1.z*d1.z + q1.w*d1.w;
#pragma unroll
    for (int o = 4; o; o >>= 1) {
        s += __shfl_xor_sync(0xffffffffu, s, o);
        d += __shfl_xor_sync(0xffffffffu, d, o);
    }
    if (lane == 0) {
        float4 es = make_float4(s, __shfl_sync(0xffffffffu, s, 8),
                                   __shfl_sync(0xffffffffu, s, 16),
                                   __shfl_sync(0xffffffffu, s, 24));
        float4 ed = make_float4(d, __shfl_sync(0xffffffffu, d, 8),
                                   __shfl_sync(0xffffffffu, d, 16),
                                   __shfl_sync(0xffffffffu, d, 24));
        g_es4[n] = es;
        g_ed4[n] = ed;
    } else {
        // non-lane0 lanes must still participate in the shfls above
        __shfl_sync(0xffffffffu, s, 8);  __shfl_sync(0xffffffffu, s, 16);
        __shfl_sync(0xffffffffu, s, 24); __shfl_sync(0xffffffffu, d, 8);
        __shfl_sync(0xffffffffu, d, 16); __shfl_sync(0xffffffffu, d, 24);
    }
}

// ---------------- CSR build ----------------
__global__ void hist_kernel(const int* __restrict__ ei) {
    int e = blockIdx.x * blockDim.x + threadIdx.x;
    if (e >= EE) return;
    int d = ei[EE + e];
    if ((unsigned)d < NN) atomicAdd(&g_cnt[d], 1);
}

__global__ void scan_block_kernel() {
    __shared__ int sh[1024];
    int i = blockIdx.x * 1024 + threadIdx.x;
    int v = (i < NN) ? g_cnt[i] : 0;
    sh[threadIdx.x] = v;
    __syncthreads();
#pragma unroll
    for (int off = 1; off < 1024; off <<= 1) {
        int t = (threadIdx.x >= off) ? sh[threadIdx.x - off] : 0;
        __syncthreads();
        sh[threadIdx.x] += t;
        __syncthreads();
    }
    if (i < NN) g_rowptr[i] = sh[threadIdx.x] - v;   // exclusive
    if (threadIdx.x == 1023) g_bsum[blockIdx.x] = sh[1023];
}

__global__ void scan_bsum_kernel() {
    __shared__ int sh[64];
    int t = threadIdx.x;
    int v = (t < NB_SCAN) ? g_bsum[t] : 0;
    sh[t] = v;
    __syncthreads();
#pragma unroll
    for (int off = 1; off < 64; off <<= 1) {
        int u = (t >= off) ? sh[t - off] : 0;
        __syncthreads();
        sh[t] += u;
        __syncthreads();
    }
    if (t < NB_SCAN) g_bsum[t] = sh[t] - v;   // exclusive block offsets
}

__global__ void scan_add_kernel() {
    int i = blockIdx.x * blockDim.x + threadIdx.x;
    if (i >= NN) return;
    int r = g_rowptr[i] + g_bsum[i >> 10];
    g_rowptr[i] = r;
    g_cursor[i] = r;
}

__global__ void scatter_kernel(const int* __restrict__ ei) {
    int e = blockIdx.x * blockDim.x + threadIdx.x;
    if (e >= EE) return;
    int s = ei[e];
    int d = ei[EE + e];
    if ((unsigned)s >= NN || (unsigned)d >= NN) return;
    int pos = atomicAdd(&g_cursor[d], 1);
    g_srcs[pos] = s;
}

// ---------------- per-node softmax stats (warp per node, no atomics) ----------------
__device__ __forceinline__ float4 leaky4(float4 a, float4 b) {
    float4 t = make_float4(a.x + b.x, a.y + b.y, a.z + b.z, a.w + b.w);
    t.x = t.x > 0.f ? t.x : t.x * NEG_SLOPE;
    t.y = t.y > 0.f ? t.y : t.y * NEG_SLOPE;
    t.z = t.z > 0.f ? t.z : t.z * NEG_SLOPE;
    t.w = t.w > 0.f ? t.w : t.w * NEG_SLOPE;
    return t;
}

__global__ void stats_kernel() {
    int n = (blockIdx.x * blockDim.x + threadIdx.x) >> 5;
    int lane = threadIdx.x & 31;
    if (n >= NN) return;
    int base = g_rowptr[n];
    int deg  = g_cnt[n];
    float4 ed = g_ed4[n];

    // pass 1: max per head (clamped at 0, matching reference init)
    float4 m = make_float4(0.f, 0.f, 0.f, 0.f);
    for (int i = lane; i < deg; i += 32) {
        int s = g_srcs[base + i];
        float4 t = leaky4(g_es4[s], ed);
        m.x = fmaxf(m.x, t.x); m.y = fmaxf(m.y, t.y);
        m.z = fmaxf(m.z, t.z); m.w = fmaxf(m.w, t.w);
    }
#pragma unroll
    for (int o = 16; o; o >>= 1) {
        m.x = fmaxf(m.x, __shfl_xor_sync(0xffffffffu, m.x, o));
        m.y = fmaxf(m.y, __shfl_xor_sync(0xffffffffu, m.y, o));
        m.z = fmaxf(m.z, __shfl_xor_sync(0xffffffffu, m.z, o));
        m.w = fmaxf(m.w, __shfl_xor_sync(0xffffffffu, m.w, o));
    }
    // pass 2: exp + sum; store per-edge weights
    float4 sum = make_float4(0.f, 0.f, 0.f, 0.f);
    for (int i = lane; i < deg; i += 32) {
        int s = g_srcs[base + i];
        float4 t = leaky4(g_es4[s], ed);
        float4 w = make_float4(__expf(t.x - m.x), __expf(t.y - m.y),
                               __expf(t.z - m.z), __expf(t.w - m.w));
        g_att4[base + i] = w;
        sum.x += w.x; sum.y += w.y; sum.z += w.z; sum.w += w.w;
    }
#pragma unroll
    for (int o = 16; o; o >>= 1) {
        sum.x += __shfl_xor_sync(0xffffffffu, sum.x, o);
        sum.y += __shfl_xor_sync(0xffffffffu, sum.y, o);
        sum.z += __shfl_xor_sync(0xffffffffu, sum.z, o);
        sum.w += __shfl_xor_sync(0xffffffffu, sum.w, o);
    }
    if (lane == 0) {
        g_rinv4[n] = make_float4(1.f / (sum.x + EPSV), 1.f / (sum.y + EPSV),
                                 1.f / (sum.z + EPSV), 1.f / (sum.w + EPSV));
    }
}

// ---------------- aggregate: warp per dst node, register accumulation ----------------
__global__ void agg_kernel(float* __restrict__ out) {
    int n = (blockIdx.x * blockDim.x + threadIdx.x) >> 5;
    int lane = threadIdx.x & 31;
    if (n >= NN) return;
    int base = g_rowptr[n];
    int deg  = g_cnt[n];

    float4 a0 = make_float4(0.f, 0.f, 0.f, 0.f);
    float4 a1 = make_float4(0.f, 0.f, 0.f, 0.f);
    bool hi = lane >= 16;   // lane covers cols lane*4 (head 0/1) and 128+lane*4 (head 2/3)

    for (int i = 0; i < deg; i++) {
        int s = g_srcs[base + i];        // broadcast
        float4 w4 = g_att4[base + i];    // broadcast
        float wa = hi ? w4.y : w4.x;
        float wb = hi ? w4.w : w4.z;
        const float4* row = reinterpret_cast<const float4*>(g_Wh + (size_t)s * OUT_COLS);
        float4 v0 = row[lane];
        float4 v1 = row[32 + lane];
        a0.x = fmaf(wa, v0.x, a0.x); a0.y = fmaf(wa, v0.y, a0.y);
        a0.z = fmaf(wa, v0.z, a0.z); a0.w = fmaf(wa, v0.w, a0.w);
        a1.x = fmaf(wb, v1.x, a1.x); a1.y = fmaf(wb, v1.y, a1.y);
        a1.z = fmaf(wb, v1.z, a1.z); a1.w = fmaf(wb, v1.w, a1.w);
    }
    float4 r = g_rinv4[n];
    float ra = hi ? r.y : r.x;
    float rb = hi ? r.w : r.z;
    a0.x *= ra; a0.y *= ra; a0.z *= ra; a0.w *= ra;
    a1.x *= rb; a1.y *= rb; a1.z *= rb; a1.w *= rb;
    float4* orow = reinterpret_cast<float4*>(out + (size_t)n * OUT_COLS);
    orow[lane] = a0;
    orow[32 + lane] = a1;
}

// ---------------- launch ----------------
extern "C" void kernel_launch(void* const* d_in, const int* in_sizes, int n_in,
                              void* d_out, int out_size) {
    const float* x     = nullptr;
    const int*   ei    = nullptr;
    const float* W     = nullptr;
    const float* a_src = nullptr;
    const float* a_dst = nullptr;
    for (int i = 0; i < n_in; i++) {
        int sz = in_sizes[i];
        if      (sz == NN * INF)            x  = (const float*)d_in[i];
        else if (sz == 2 * EE)              ei = (const int*)d_in[i];
        else if (sz == HEADS * INF * OUTF)  W  = (const float*)d_in[i];
        else if (sz == HEADS * OUTF) {
            if (!a_src) a_src = (const float*)d_in[i];
            else        a_dst = (const float*)d_in[i];
        }
    }
    float* out = (float*)d_out;
    (void)out_size;

    init_kernel<<<(NN + 255) / 256, 256>>>();
    {
        dim3 grid((NN + 63) / 64, HEADS);
        gemm_kernel<<<grid, 256>>>(x, W);
    }
    escore_kernel<<<((size_t)NN * 32 + 255) / 256, 256>>>(a_src, a_dst);
    hist_kernel<<<(EE + 255) / 256, 256>>>(ei);
    scan_block_kernel<<<NB_SCAN, 1024>>>();
    scan_bsum_kernel<<<1, 64>>>();
    scan_add_kernel<<<(NN + 255) / 256, 256>>>();
    scatter_kernel<<<(EE + 255) / 256, 256>>>(ei);
    stats_kernel<<<((size_t)NN * 32 + 255) / 256, 256>>>();
    agg_kernel<<<((size_t)NN * 32 + 255) / 256, 256>>>(out);
}